// round 16
// baseline (speedup 1.0000x reference)
#include <cuda_runtime.h>
#include <cuda_fp16.h>
#include <math.h>
#include <stdint.h>
#include <stddef.h>

// ---------------------------------------------------------------------------
// TWSABlock round 16: R15 base (best 728.2 us). Single delta: hgemm tile
// 128x128 re-partitioned across 16 warps (512 threads, warp tile 32x32,
// launch_bounds(512,2) -> 64 regs, 32 warps/SM). Traffic/mma order identical.
// ---------------------------------------------------------------------------

#define HW 4096
#define NB 16
#define CC 256
#define NTOK (NB * HW)
#define EPS 1e-5f

// ============================ small helpers ================================
__device__ __forceinline__ uint32_t smem_u32(const void* p) {
    uint32_t a;
    asm("{ .reg .u64 t; cvta.to.shared.u64 t, %1; cvt.u32.u64 %0, t; }"
        : "=r"(a) : "l"(p));
    return a;
}
__device__ __forceinline__ void ldsm4(uint32_t addr, uint32_t* r) {
    asm volatile("ldmatrix.sync.aligned.m8n8.x4.shared.b16 {%0,%1,%2,%3}, [%4];"
                 : "=r"(r[0]), "=r"(r[1]), "=r"(r[2]), "=r"(r[3]) : "r"(addr));
}
__device__ __forceinline__ void ldsm4t(uint32_t addr, uint32_t* r) {
    asm volatile("ldmatrix.sync.aligned.m8n8.x4.trans.shared.b16 {%0,%1,%2,%3}, [%4];"
                 : "=r"(r[0]), "=r"(r[1]), "=r"(r[2]), "=r"(r[3]) : "r"(addr));
}
__device__ __forceinline__ void mma16816(float* c, const uint32_t* a,
                                         uint32_t b0, uint32_t b1) {
    asm volatile(
        "mma.sync.aligned.m16n8k16.row.col.f32.f16.f16.f32 "
        "{%0,%1,%2,%3}, {%4,%5,%6,%7}, {%8,%9}, {%0,%1,%2,%3};"
        : "+f"(c[0]), "+f"(c[1]), "+f"(c[2]), "+f"(c[3])
        : "r"(a[0]), "r"(a[1]), "r"(a[2]), "r"(a[3]), "r"(b0), "r"(b1));
}
__device__ __forceinline__ uint32_t packh2(float a, float b) {
    __half2 t = __halves2half2(__float2half_rn(a), __float2half_rn(b));
    return *reinterpret_cast<uint32_t*>(&t);
}
#define CP_ASYNC16(dst, src) \
    asm volatile("cp.async.cg.shared.global [%0], [%1], 16;" :: "r"(dst), "l"(src))
#define CP_COMMIT() asm volatile("cp.async.commit_group;" ::: "memory")

// ============================== scratch ====================================
__device__ float g_x1[NTOK * CC];
__device__ float g_x2[NTOK * CC];
__device__ __half g_xh  [NTOK * CC];
__device__ __half g_t1h [NTOK * CC];
__device__ __half g_t2h [NTOK * CC];
__device__ __half g_x1nh[NTOK * CC];
__device__ __half g_qkvh[NTOK * 3 * CC];
__device__ __half g_obh [NTOK * CC];
__device__ __half g_x2nh[NTOK * CC];
__device__ __half g_hidh[NTOK * 4 * CC];
__device__ __half g_w1h[CC * CC];
__device__ __half g_w3h[CC * CC];
__device__ __half g_wph[CC * CC];
__device__ __half g_wqh[3 * CC * CC];
__device__ __half g_m1h[4 * CC * CC];
__device__ __half g_w2h[CC * 4 * CC];
__device__ float g_b1f[CC];
__device__ float g_dwf[CC * 9];
__device__ float g_dbf[CC];
__device__ float g_qkvbf[3 * CC];
__device__ float g_m1bf[4 * CC];

// ================== prep + input-convert (merged launch) ===================
__global__ void __launch_bounds__(256) prep_kernel(
    const float* __restrict__ conv1_w, const float* __restrict__ conv1_b,
    const float* __restrict__ bn1_g,  const float* __restrict__ bn1_b,
    const float* __restrict__ bn1_m,  const float* __restrict__ bn1_v,
    const float* __restrict__ dw_w,   const float* __restrict__ dw_b,
    const float* __restrict__ bn2_g,  const float* __restrict__ bn2_b,
    const float* __restrict__ bn2_m,  const float* __restrict__ bn2_v,
    const float* __restrict__ conv3_w,
    const float* __restrict__ proj_w,
    const float* __restrict__ mlp_w2,
    const float* __restrict__ qkv_w,  const float* __restrict__ qkv_b,
    const float* __restrict__ ln1_g,  const float* __restrict__ ln1_b,
    const float* __restrict__ mlp_w1, const float* __restrict__ mlp_b1,
    const float* __restrict__ ln2_g,  const float* __restrict__ ln2_b,
    const float* __restrict__ x, __half* __restrict__ xh)
{
    __shared__ float red[8];
    const int blk = blockIdx.x;
    const int tid = threadIdx.x;

    if (blk >= 1024) {
        __shared__ float sm[64 * 65];
        const int cid = blk - 1024;
        const int b  = cid >> 8;
        const int c0 = ((cid >> 6) & 3) * 64;
        const int p0 = (cid & 63) * 64;
        #pragma unroll
        for (int w = 0; w < 16; w++) {
            const int idx = tid + 256 * w;
            const int cl = idx >> 6, pl = idx & 63;
            sm[cl * 65 + pl] = x[((size_t)(b * 256 + c0 + cl)) * HW + p0 + pl];
        }
        __syncthreads();
        #pragma unroll
        for (int w = 0; w < 8; w++) {
            const int idx = tid + 256 * w;
            const int pl = idx >> 5, c2 = (idx & 31) * 2;
            const __half2 v = __halves2half2(
                __float2half_rn(sm[c2 * 65 + pl]),
                __float2half_rn(sm[(c2 + 1) * 65 + pl]));
            *reinterpret_cast<__half2*>(
                &xh[((size_t)(b * HW + p0 + pl)) * 256 + c0 + c2]) = v;
        }
        return;
    }

    const int r = blk;
    if (r < 256) {
        float inv1 = bn1_g[r] * rsqrtf(bn1_v[r] + EPS);
        g_w1h[r * 256 + tid] = __float2half_rn(conv1_w[r * 256 + tid] * inv1);
        g_w3h[r * 256 + tid] = __float2half_rn(conv3_w[r * 256 + tid]);
        g_wph[r * 256 + tid] = __float2half_rn(proj_w[r * 256 + tid]);
        #pragma unroll
        for (int k = 0; k < 4; k++)
            g_w2h[r * 1024 + tid + 256 * k] =
                __float2half_rn(mlp_w2[r * 1024 + tid + 256 * k]);
        if (tid == 0) g_b1f[r] = conv1_b[r] * inv1 + bn1_b[r] - bn1_m[r] * inv1;
        float inv2 = bn2_g[r] * rsqrtf(bn2_v[r] + EPS);
        if (tid < 9) g_dwf[r * 9 + tid] = dw_w[r * 9 + tid] * inv2;
        if (tid == 0) g_dbf[r] = dw_b[r] * inv2 + bn2_b[r] - bn2_m[r] * inv2;
    }
    if (r < 768) {
        float w = qkv_w[r * 256 + tid];
        g_wqh[r * 256 + tid] = __float2half_rn(w * ln1_g[tid]);
        float part = w * ln1_b[tid];
        #pragma unroll
        for (int o = 16; o; o >>= 1) part += __shfl_xor_sync(0xffffffffu, part, o);
        if ((tid & 31) == 0) red[tid >> 5] = part;
        __syncthreads();
        if (tid == 0) {
            float s = 0.f;
            #pragma unroll
            for (int w2 = 0; w2 < 8; w2++) s += red[w2];
            g_qkvbf[r] = qkv_b[r] + s;
        }
        __syncthreads();
    }
    if (r < 1024) {
        float w = mlp_w1[r * 256 + tid];
        g_m1h[r * 256 + tid] = __float2half_rn(w * ln2_g[tid]);
        float part = w * ln2_b[tid];
        #pragma unroll
        for (int o = 16; o; o >>= 1) part += __shfl_xor_sync(0xffffffffu, part, o);
        if ((tid & 31) == 0) red[tid >> 5] = part;
        __syncthreads();
        if (tid == 0) {
            float s = 0.f;
            #pragma unroll
            for (int w2 = 0; w2 < 8; w2++) s += red[w2];
            g_m1bf[r] = mlp_b1[r] + s;
        }
    }
}

// ========================= fp16 mma.sync GEMM ==============================
// Block tile 128x128, BK=64, 512 threads = 16 warps (4m x 4n), warp 32x32.
// 3-stage cp.async ring, ONE __syncthreads per iteration, prefetch depth 2.
constexpr int ROWB  = 144;
constexpr int PLANE = 128 * ROWB;          // 18432 B
constexpr int STAGE = 2 * PLANE;           // 36864 B (A, W)
constexpr int GEMM_SMEM = 3 * STAGE;       // 110592 B

// EP: 0 bias->fp16 ; 1 bias+res(tok fp32)->fp32 tok ; 2 gelu(bias)->fp16 ;
//     3 bias+res(NCHW fp32 via smem transpose)->fp32 tok ;
//     4 bias+res(tok fp32) -> NCHW fp32 out (smem transpose)
template<int K, int EP>
__global__ void __launch_bounds__(512, 2) hgemm(
    const __half* __restrict__ A, const __half* __restrict__ W,
    const float* __restrict__ bias, const float* __restrict__ res,
    float* __restrict__ outf, __half* __restrict__ outh, int N)
{
    extern __shared__ __align__(128) char smem[];
    const uint32_t sb = smem_u32(smem);
    const int n0  = blockIdx.x * 128;
    const int m0  = blockIdx.y * 128;
    const int tid = threadIdx.x;
    const int lane = tid & 31, wid = tid >> 5;
    const int wm = wid >> 2, wn = wid & 3;

    const char* srcA = (const char*)(A + (size_t)m0 * K);
    const char* srcW = (const char*)(W + (size_t)n0 * K);

    float c[2][4][4];
    #pragma unroll
    for (int i = 0; i < 2; i++)
        #pragma unroll
        for (int j = 0; j < 4; j++)
            #pragma unroll
            for (int r = 0; r < 4; r++) c[i][j][r] = 0.f;

    auto load_stage = [&](int s, int buf) {
        const uint32_t dst0 = sb + (uint32_t)buf * STAGE;
        const int c0b = s * 128;
        #pragma unroll
        for (int j = 0; j < 2; ++j) {
            const int e = tid + 512 * j;          // 0..1023 per plane
            const int row = e >> 3, q = e & 7;
            CP_ASYNC16(dst0 + row * ROWB + q * 16,
                       srcA + (size_t)row * (K * 2) + c0b + q * 16);
            CP_ASYNC16(dst0 + PLANE + row * ROWB + q * 16,
                       srcW + (size_t)row * (K * 2) + c0b + q * 16);
        }
        CP_COMMIT();
    };

    const uint32_t aoff = (uint32_t)((lane & 15) * ROWB + (lane >> 4) * 16
                                     + wm * 32 * ROWB);
    const uint32_t boff = (uint32_t)(((lane & 7) + ((lane >> 4) << 3)) * ROWB
                                     + ((lane >> 3) & 1) * 16 + wn * 32 * ROWB);

    constexpr int NS = K / 64;
    load_stage(0, 0);
    load_stage(1, 1);
    int cbuf = 0;
    for (int s = 0; s < NS; ++s) {
        if (s + 1 < NS) {
            asm volatile("cp.async.wait_group 1;" ::: "memory");
        } else {
            asm volatile("cp.async.wait_group 0;" ::: "memory");
        }
        __syncthreads();

        int nbuf = cbuf + 2; if (nbuf >= 3) nbuf -= 3;
        if (s + 2 < NS) load_stage(s + 2, nbuf); else CP_COMMIT();

        const uint32_t base = sb + (uint32_t)cbuf * STAGE;
        #pragma unroll
        for (int k16 = 0; k16 < 4; ++k16) {
            const uint32_t kb = k16 * 32;
            uint32_t a[2][4], b[2][4];
            #pragma unroll
            for (int mt = 0; mt < 2; ++mt)
                ldsm4(base + aoff + mt * 16 * ROWB + kb, a[mt]);
            #pragma unroll
            for (int np = 0; np < 2; ++np)
                ldsm4(base + PLANE + boff + np * 16 * ROWB + kb, b[np]);
            #pragma unroll
            for (int mt = 0; mt < 2; ++mt)
                #pragma unroll
                for (int nt = 0; nt < 4; ++nt)
                    mma16816(c[mt][nt], a[mt],
                             b[nt >> 1][(nt & 1) * 2], b[nt >> 1][(nt & 1) * 2 + 1]);
        }
        cbuf = cbuf + 1; if (cbuf >= 3) cbuf -= 3;
    }
    __syncthreads();

    // ------------------------------ epilogue -------------------------------
    const int gr = lane >> 2, gc = (lane & 3) << 1;

    if (EP <= 2) {
        #pragma unroll
        for (int mt = 0; mt < 2; ++mt) {
            #pragma unroll
            for (int nt = 0; nt < 4; ++nt) {
                const int n = n0 + wn * 32 + nt * 8 + gc;
                const float2 b2 = *reinterpret_cast<const float2*>(&bias[n]);
                #pragma unroll
                for (int rh = 0; rh < 2; ++rh) {
                    const int m = m0 + wm * 32 + mt * 16 + gr + rh * 8;
                    float vx = c[mt][nt][rh * 2 + 0] + b2.x;
                    float vy = c[mt][nt][rh * 2 + 1] + b2.y;
                    const size_t off = (size_t)m * N + n;
                    if (EP == 1) {
                        const float2 r2 = *reinterpret_cast<const float2*>(&res[off]);
                        float2 o; o.x = vx + r2.x; o.y = vy + r2.y;
                        *reinterpret_cast<float2*>(&outf[off]) = o;
                    } else {
                        if (EP == 2) {
                            vx = vx * normcdff(vx);
                            vy = vy * normcdff(vy);
                        }
                        *reinterpret_cast<__half2*>(&outh[off]) =
                            __halves2half2(__float2half_rn(vx), __float2half_rn(vy));
                    }
                }
            }
        }
    } else if (EP == 3) {
        float* Rs = reinterpret_cast<float*>(smem);
        const int bb = m0 >> 12, p0 = m0 & 4095;
        #pragma unroll
        for (int nh = 0; nh < 2; ++nh) {
            __syncthreads();
            for (int e = tid; e < 2048; e += 512) {
                const int row = e >> 5, q = e & 31;
                *reinterpret_cast<float4*>(&Rs[row * 132 + q * 4]) =
                    *reinterpret_cast<const float4*>(
                        &res[((size_t)(bb * 256 + n0 + nh * 64 + row)) * HW + p0 + q * 4]);
            }
            __syncthreads();
            if ((wn >> 1) == nh) {
                #pragma unroll
                for (int mt = 0; mt < 2; ++mt) {
                    #pragma unroll
                    for (int nt = 0; nt < 4; ++nt) {
                        const int nl = (wn & 1) * 32 + nt * 8 + gc;
                        const int n = n0 + nh * 64 + nl;
                        const float2 b2 = *reinterpret_cast<const float2*>(&bias[n]);
                        #pragma unroll
                        for (int rh = 0; rh < 2; ++rh) {
                            const int ml = wm * 32 + mt * 16 + gr + rh * 8;
                            float2 o;
                            o.x = c[mt][nt][rh * 2 + 0] + b2.x + Rs[nl * 132 + ml];
                            o.y = c[mt][nt][rh * 2 + 1] + b2.y + Rs[(nl + 1) * 132 + ml];
                            *reinterpret_cast<float2*>(&outf[(size_t)(m0 + ml) * 256 + n]) = o;
                        }
                    }
                }
            }
        }
    } else {  // EP == 4
        float* Cs = reinterpret_cast<float*>(smem);
        const int bb = m0 >> 12, p0 = m0 & 4095;
        #pragma unroll
        for (int nh = 0; nh < 2; ++nh) {
            __syncthreads();
            if ((wn >> 1) == nh) {
                #pragma unroll
                for (int mt = 0; mt < 2; ++mt) {
                    #pragma unroll
                    for (int nt = 0; nt < 4; ++nt) {
                        const int nl = (wn & 1) * 32 + nt * 8 + gc;
                        const int n = n0 + nh * 64 + nl;
                        const float2 b2 = *reinterpret_cast<const float2*>(&bias[n]);
                        #pragma unroll
                        for (int rh = 0; rh < 2; ++rh) {
                            const int ml = wm * 32 + mt * 16 + gr + rh * 8;
                            const size_t roff = (size_t)(m0 + ml) * 256 + n;
                            const float2 r2 = *reinterpret_cast<const float2*>(&res[roff]);
                            Cs[nl * 132 + ml]       = c[mt][nt][rh * 2 + 0] + b2.x + r2.x;
                            Cs[(nl + 1) * 132 + ml] = c[mt][nt][rh * 2 + 1] + b2.y + r2.y;
                        }
                    }
                }
            }
            __syncthreads();
            for (int e = tid; e < 2048; e += 512) {
                const int row = e >> 5, q = e & 31;
                *reinterpret_cast<float4*>(
                    &outf[((size_t)(bb * 256 + n0 + nh * 64 + row)) * HW + p0 + q * 4]) =
                    *reinterpret_cast<const float4*>(&Cs[row * 132 + q * 4]);
            }
        }
    }
}

// ============== dw conv 3x3 (sliding window, half2 datapath) ===============
__global__ void __launch_bounds__(256, 3) dwconv_kernel(
    const __half* __restrict__ in, __half* __restrict__ oh)
{
    const int by = blockIdx.x;
    const int b = by >> 6, y = by & 63;
    const int tid = threadIdx.x;
    const int c4 = tid & 63;
    const int xq = tid >> 6;

    __half2 w2[9][2];
    #pragma unroll
    for (int k = 0; k < 9; k++)
        #pragma unroll
        for (int j = 0; j < 2; j++)
            w2[k][j] = __floats2half2_rn(g_dwf[(c4 * 4 + 2 * j) * 9 + k],
                                         g_dwf[(c4 * 4 + 2 * j + 1) * 9 + k]);
    const __half2 bs0 = __floats2half2_rn(g_dbf[c4 * 4],     g_dbf[c4 * 4 + 1]);
    const __half2 bs1 = __floats2half2_rn(g_dbf[c4 * 4 + 2], g_dbf[c4 * 4 + 3]);

    const __half* pM = in + ((size_t)(b * HW + y * 64)) * 256 + c4 * 4;
    const __half* pU = pM - 64 * 256;
    const __half* pD = pM + 64 * 256;
    const bool hasU = y > 0, hasD = y < 63;

    __half2 L[3][2], M[3][2], R[3][2];
    const __half2 z2 = __float2half2_rn(0.f);

    auto loadcol = [&](int xx, __half2 col[3][2]) {
        #pragma unroll
        for (int r = 0; r < 3; r++) {
            const bool ok = (r == 0) ? hasU : ((r == 2) ? hasD : true);
            if (ok) {
                const __half* p = (r == 0) ? pU : ((r == 1) ? pM : pD);
                const uint2 u = *reinterpret_cast<const uint2*>(p + xx * 256);
                col[r][0] = *reinterpret_cast<const __half2*>(&u.x);
                col[r][1] = *reinterpret_cast<const __half2*>(&u.y);
            } else {
                col[r][0] = z2;
                col[r][1] = z2;
            }
        }
    };

    const int x0 = xq * 16;
    if (x0 > 0) loadcol(x0 - 1, L);
    else {
        #pragma unroll
        for (int r = 0; r < 3; r++) { L[r][0] = z2; L[r][1] = z2; }
    }
    loadcol(x0, M);

    #pragma unroll
    for (int xi = 0; xi < 16; ++xi) {
        const int x = x0 + xi;
        if (x < 63) loadcol(x + 1, R);
        else {
            #pragma unroll
            for (int r = 0; r < 3; r++) { R[r][0] = z2; R[r][1] = z2; }
        }
        __half2 a0 = bs0, a1 = bs1;
        #pragma unroll
        for (int r = 0; r < 3; r++) {
            a0 = __hfma2(w2[r * 3 + 0][0], L[r][0], a0);
            a1 = __hfma2(w2[r * 3 + 0][1], L[r][1], a1);
            a0 = __hfma2(w2[r * 3 + 1][0], M[r][0], a0);
            a1 = __hfma2(w2[r * 3 + 1][1], M[r][1], a1);
            a0 = __hfma2(w2[r * 3 + 2][0], R[r][0], a0);
            a1 = __hfma2(w2[r * 3 + 2][1], R[r][1], a1);
        }
        uint2 uo;
        uo.x = *reinterpret_cast<uint32_t*>(&a0);
        uo.y = *reinterpret_cast<uint32_t*>(&a1);
        *reinterpret_cast<uint2*>(
            const_cast<__half*>(oh + ((size_t)(b * HW + y * 64 + x)) * 256 + c4 * 4)) = uo;
        #pragma unroll
        for (int r = 0; r < 3; r++) {
            L[r][0] = M[r][0]; L[r][1] = M[r][1];
            M[r][0] = R[r][0]; M[r][1] = R[r][1];
        }
    }
}

// ===================== LayerNorm + fp16 convert ============================
__global__ void __launch_bounds__(256) ln_split(
    const float* __restrict__ x, __half* __restrict__ oh)
{
    const int warp = threadIdx.x >> 5, lane = threadIdx.x & 31;
    const int tok = blockIdx.x * 8 + warp;
    const float* row = x + (size_t)tok * 256;
    const float4 v0 = *reinterpret_cast<const float4*>(&row[lane * 8]);
    const float4 v1 = *reinterpret_cast<const float4*>(&row[lane * 8 + 4]);
    float s = v0.x + v0.y + v0.z + v0.w + v1.x + v1.y + v1.z + v1.w;
    float s2 = v0.x * v0.x + v0.y * v0.y + v0.z * v0.z + v0.w * v0.w
             + v1.x * v1.x + v1.y * v1.y + v1.z * v1.z + v1.w * v1.w;
    #pragma unroll
    for (int o = 16; o; o >>= 1) {
        s  += __shfl_xor_sync(0xffffffffu, s,  o);
        s2 += __shfl_xor_sync(0xffffffffu, s2, o);
    }
    const float mu = s * (1.f / 256.f);
    const float rs = rsqrtf(s2 * (1.f / 256.f) - mu * mu + EPS);

    float v[8] = {v0.x, v0.y, v0.z, v0.w, v1.x, v1.y, v1.z, v1.w};
    uint4 uh;
    uh.x = packh2((v[0] - mu) * rs, (v[1] - mu) * rs);
    uh.y = packh2((v[2] - mu) * rs, (v[3] - mu) * rs);
    uh.z = packh2((v[4] - mu) * rs, (v[5] - mu) * rs);
    uh.w = packh2((v[6] - mu) * rs, (v[7] - mu) * rs);
    *reinterpret_cast<uint4*>(&oh[(size_t)tok * 256 + lane * 8]) = uh;
}

// ================== window attention on tensor cores =======================
constexpr int APAD  = 72;
constexpr int APADB = APAD * 2;
constexpr int HEAD_SMEM = 2 * 64 * APADB;
constexpr int ATTN_SMEM = 4 * HEAD_SMEM;     // 73728 B

__global__ void __launch_bounds__(128, 3) attn_mma(
    const __half* __restrict__ qkv, __half* __restrict__ oh)
{
    extern __shared__ __align__(128) char asmem[];
    const int win = blockIdx.x;
    const int b = win >> 6, wrem = win & 63;
    const int pbase = b * HW + (wrem >> 3) * 512 + (wrem & 7) * 8;
    const int tid = threadIdx.x;
    const int wid = tid >> 5, lane = tid & 31;
    const int gr = lane >> 2, gc = (lane & 3) << 1;

    const uint32_t qbase = smem_u32(asmem) + wid * HEAD_SMEM;
    const uint32_t kbase = qbase + 64 * APADB;
    __half* Qs = reinterpret_cast<__half*>(asmem) + wid * (HEAD_SMEM / 2);
    __half* Ks = Qs + 64 * APAD;

    const int qo = wid * 64, ko = 256 + wid * 64, vo = 512 + wid * 64;

    for (int e = lane; e < 512; e += 32) {
        const int t = e >> 3, q = e & 7;
        const int p = pbase + ((t >> 3) << 6) + (t & 7);
        *reinterpret_cast<uint4*>(&Qs[t * APAD + q * 8]) =
            *reinterpret_cast<const uint4*>(&qkv[(size_t)p * 768 + qo + q * 8]);
        *reinterpret_cast<uint4*>(&Ks[t * APAD + q * 8]) =
            *reinterpret_cast<const uint4*>(&qkv[(size_t)p * 768 + ko + q * 8]);
    }
    __syncwarp();

    const uint32_t aoff = (uint32_t)((lane & 15) * APADB + (lane >> 4) * 16);
    const uint32_t boff = (uint32_t)(((lane & 7) + ((lane >> 4) << 3)) * APADB
                                     + ((lane >> 3) & 1) * 16);

    float s[4][8][4];
    #pragma unroll
    for (int i = 0; i < 4; i++)
        #pragma unroll
        for (int j = 0; j < 8; j++)
            #pragma unroll
            for (int r = 0; r < 4; r++) s[i][j][r] = 0.f;

    #pragma unroll
    for (int k16 = 0; k16 < 4; ++k16) {
        const uint32_t kb = k16 * 32;
        uint32_t a[4][4], bf[4][4];
        #pragma unroll
        for (int mt = 0; mt < 4; ++mt)
            ldsm4(qbase + aoff + mt * 16 * APADB + kb, a[mt]);
        #pragma unroll
        for (int np = 0; np < 4; ++np)
            ldsm4(kbase + boff + np * 16 * APADB + kb, bf[np]);
        #pragma unroll
        for (int mt = 0; mt < 4; ++mt)
            #pragma unroll
            for (int nt = 0; nt < 8; ++nt)
                mma16816(s[mt][nt], a[mt],
                         bf[nt >> 1][(nt & 1) * 2], bf[nt >> 1][(nt & 1) * 2 + 1]);
    }

    const float sc = 0.125f;
    #pragma unroll
    for (int mt = 0; mt < 4; ++mt) {
        #pragma unroll
        for (int rh = 0; rh < 2; ++rh) {
            float mx = -1e30f;
            #pragma unroll
            for (int nt = 0; nt < 8; ++nt) {
                s[mt][nt][rh * 2]     *= sc;
                s[mt][nt][rh * 2 + 1] *= sc;
                mx = fmaxf(mx, fmaxf(s[mt][nt][rh * 2], s[mt][nt][rh * 2 + 1]));
            }
            mx = fmaxf(mx, __shfl_xor_sync(0xffffffffu, mx, 1));
            mx = fmaxf(mx, __shfl_xor_sync(0xffffffffu, mx, 2));
            float sum = 0.f;
            #pragma unroll
            for (int nt = 0; nt < 8; ++nt) {
                s[mt][nt][rh * 2]     = __expf(s[mt][nt][rh * 2] - mx);
                s[mt][nt][rh * 2 + 1] = __expf(s[mt][nt][rh * 2 + 1] - mx);
                sum += s[mt][nt][rh * 2] + s[mt][nt][rh * 2 + 1];
            }
            sum += __shfl_xor_sync(0xffffffffu, sum, 1);
            sum += __shfl_xor_sync(0xffffffffu, sum, 2);
            const float inv = 1.f / sum;
            #pragma unroll
            for (int nt = 0; nt < 8; ++nt) {
                s[mt][nt][rh * 2]     *= inv;
                s[mt][nt][rh * 2 + 1] *= inv;
            }
        }
    }

    uint32_t ap[4][4][4];
    #pragma unroll
    for (int mt = 0; mt < 4; ++mt)
        #pragma unroll
        for (int kt = 0; kt < 4; ++kt) {
            ap[mt][kt][0] = packh2(s[mt][2 * kt][0],     s[mt][2 * kt][1]);
            ap[mt][kt][1] = packh2(s[mt][2 * kt][2],     s[mt][2 * kt][3]);
            ap[mt][kt][2] = packh2(s[mt][2 * kt + 1][0], s[mt][2 * kt + 1][1]);
            ap[mt][kt][3] = packh2(s[mt][2 * kt + 1][2], s[mt][2 * kt + 1][3]);
        }

    // reuse s as O accumulator
    #pragma unroll
    for (int i = 0; i < 4; i++)
        #pragma unroll
        for (int j = 0; j < 8; j++)
            #pragma unroll
            for (int r = 0; r < 4; r++) s[i][j][r] = 0.f;

    __syncwarp();
    for (int e = lane; e < 512; e += 32) {
        const int t = e >> 3, q = e & 7;
        const int p = pbase + ((t >> 3) << 6) + (t & 7);
        *reinterpret_cast<uint4*>(&Ks[t * APAD + q * 8]) =
            *reinterpret_cast<const uint4*>(&qkv[(size_t)p * 768 + vo + q * 8]);
    }
    __syncwarp();

    const uint32_t vtoff = (uint32_t)((lane & 15) * APADB + (lane >> 4) * 16);

    #pragma unroll
    for (int kt = 0; kt < 4; ++kt) {
        uint32_t bf[4][4];
        #pragma unroll
        for (int np = 0; np < 4; ++np)
            ldsm4t(kbase + vtoff + kt * 16 * APADB + np * 32, bf[np]);
        #pragma unroll
        for (int mt = 0; mt < 4; ++mt)
            #pragma unroll
            for (int nt = 0; nt < 8; ++nt)
                mma16816(s[mt][nt], ap[mt][kt],
                         bf[nt >> 1][(nt & 1) * 2], bf[nt >> 1][(nt & 1) * 2 + 1]);
    }

    #pragma unroll
    for (int mt = 0; mt < 4; ++mt)
        #pragma unroll
        for (int rh = 0; rh < 2; ++rh) {
            const int t = mt * 16 + gr + rh * 8;
            const int p = pbase + ((t >> 3) << 6) + (t & 7);
            #pragma unroll
            for (int nt = 0; nt < 8; ++nt) {
                const int d = nt * 8 + gc;
                *reinterpret_cast<__half2*>(&oh[(size_t)p * 256 + qo + d]) =
                    __halves2half2(__float2half_rn(s[mt][nt][rh * 2]),
                                   __float2half_rn(s[mt][nt][rh * 2 + 1]));
            }
        }
}

// =============================== launcher ==================================
extern "C" void kernel_launch(void* const* d_in, const int* in_sizes, int n_in,
                              void* d_out, int out_size)
{
    (void)in_sizes; (void)n_in; (void)out_size;
    const float* x       = (const float*)d_in[0];
    const float* conv1_w = (const float*)d_in[1];
    const float* conv1_b = (const float*)d_in[2];
    const float* bn1_g   = (const float*)d_in[3];
    const float* bn1_b   = (const float*)d_in[4];
    const float* bn1_m   = (const float*)d_in[5];
    const float* bn1_v   = (const float*)d_in[6];
    const float* dw_w    = (const float*)d_in[7];
    const float* dw_b    = (const float*)d_in[8];
    const float* bn2_g   = (const float*)d_in[9];
    const float* bn2_b   = (const float*)d_in[10];
    const float* bn2_m   = (const float*)d_in[11];
    const float* bn2_v   = (const float*)d_in[12];
    const float* conv3_w = (const float*)d_in[13];
    const float* conv3_b = (const float*)d_in[14];
    const float* ln1_g   = (const float*)d_in[15];
    const float* ln1_b   = (const float*)d_in[16];
    const float* qkv_w   = (const float*)d_in[17];
    const float* qkv_b   = (const float*)d_in[18];
    const float* proj_w  = (const float*)d_in[19];
    const float* proj_b  = (const float*)d_in[20];
    const float* ln2_g   = (const float*)d_in[21];
    const float* ln2_b   = (const float*)d_in[22];
    const float* mlp_w1  = (const float*)d_in[23];
    const float* mlp_b1  = (const float*)d_in[24];
    const float* mlp_w2  = (const float*)d_in[25];
    const float* mlp_b2  = (const float*)d_in[26];
    float* out = (float*)d_out;

    float *x1, *x2, *b1f, *qkvbf, *m1bf;
    __half *xh, *t1h, *t2h, *x1nh, *qkvh, *obh, *x2nh, *hidh;
    __half *w1h, *w3h, *wph, *wqh, *m1h, *w2h;
    cudaGetSymbolAddress((void**)&x1,   g_x1);
    cudaGetSymbolAddress((void**)&x2,   g_x2);
    cudaGetSymbolAddress((void**)&xh,   g_xh);
    cudaGetSymbolAddress((void**)&t1h,  g_t1h);
    cudaGetSymbolAddress((void**)&t2h,  g_t2h);
    cudaGetSymbolAddress((void**)&x1nh, g_x1nh);
    cudaGetSymbolAddress((void**)&qkvh, g_qkvh);
    cudaGetSymbolAddress((void**)&obh,  g_obh);
    cudaGetSymbolAddress((void**)&x2nh, g_x2nh);
    cudaGetSymbolAddress((void**)&hidh, g_hidh);
    cudaGetSymbolAddress((void**)&w1h,  g_w1h);
    cudaGetSymbolAddress((void**)&w3h,  g_w3h);
    cudaGetSymbolAddress((void**)&wph,  g_wph);
    cudaGetSymbolAddress((void**)&wqh,  g_wqh);
    cudaGetSymbolAddress((void**)&m1h,  g_m1h);
    cudaGetSymbolAddress((void**)&w2h,  g_w2h);
    cudaGetSymbolAddress((void**)&b1f,   g_b1f);
    cudaGetSymbolAddress((void**)&qkvbf, g_qkvbf);
    cudaGetSymbolAddress((void**)&m1bf,  g_m1bf);

    cudaFuncSetAttribute(hgemm<256, 0>,
        cudaFuncAttributeMaxDynamicSharedMemorySize, GEMM_SMEM);
    cudaFuncSetAttribute(hgemm<256, 1>,
        cudaFuncAttributeMaxDynamicSharedMemorySize, GEMM_SMEM);
    cudaFuncSetAttribute(hgemm<256, 2>,
        cudaFuncAttributeMaxDynamicSharedMemorySize, GEMM_SMEM);
    cudaFuncSetAttribute(hgemm<256, 3>,
        cudaFuncAttributeMaxDynamicSharedMemorySize, GEMM_SMEM);
    cudaFuncSetAttribute(hgemm<1024, 4>,
        cudaFuncAttributeMaxDynamicSharedMemorySize, GEMM_SMEM);
    cudaFuncSetAttribute(attn_mma,
        cudaFuncAttributeMaxDynamicSharedMemorySize, ATTN_SMEM);

    // 0) prep (weights) + input convert, single launch
    prep_kernel<<<5120, 256>>>(conv1_w, conv1_b, bn1_g, bn1_b, bn1_m, bn1_v,
                               dw_w, dw_b, bn2_g, bn2_b, bn2_m, bn2_v,
                               conv3_w, proj_w, mlp_w2,
                               qkv_w, qkv_b, ln1_g, ln1_b,
                               mlp_w1, mlp_b1, ln2_g, ln2_b,
                               x, xh);

    // 1) conv1 + BN1 -> t1 fp16
    hgemm<256, 0><<<dim3(2, 512), 512, GEMM_SMEM>>>(
        xh, w1h, b1f, nullptr, nullptr, t1h, 256);
    // 2) dw3x3 + BN2 -> t2 fp16 (half2 datapath, 3 CTA/SM)
    dwconv_kernel<<<1024, 256>>>(t1h, t2h);
    // 3) conv3 + residual(x NCHW) -> x1 fp32 token-major
    hgemm<256, 3><<<dim3(2, 512), 512, GEMM_SMEM>>>(
        t2h, w3h, conv3_b, x, x1, nullptr, 256);
    // 4) LN1 -> x1n fp16
    ln_split<<<8192, 256>>>(x1, x1nh);
    // 5) QKV -> qkv fp16 [tok][768]
    hgemm<256, 0><<<dim3(6, 512), 512, GEMM_SMEM>>>(
        x1nh, wqh, qkvbf, nullptr, nullptr, qkvh, 768);
    // 6) window attention (tensor cores) -> ob fp16
    attn_mma<<<1024, 128, ATTN_SMEM>>>(qkvh, obh);
    // 7) proj + residual(x1) -> x2 fp32
    hgemm<256, 1><<<dim3(2, 512), 512, GEMM_SMEM>>>(
        obh, wph, proj_b, x1, x2, nullptr, 256);
    // 8) LN2 -> x2n fp16
    ln_split<<<8192, 256>>>(x2, x2nh);
    // 9) MLP1 + GELU -> hid fp16 [tok][1024]
    hgemm<256, 2><<<dim3(8, 512), 512, GEMM_SMEM>>>(
        x2nh, m1h, m1bf, nullptr, nullptr, hidh, 1024);
    // 10) MLP2 + residual(x2) -> out NCHW fp32
    hgemm<1024, 4><<<dim3(2, 512), 512, GEMM_SMEM>>>(
        hidh, w2h, mlp_b2, x2, out, nullptr, 256);
}

// round 17
// speedup vs baseline: 1.0394x; 1.0394x over previous
#include <cuda_runtime.h>
#include <cuda_fp16.h>
#include <math.h>
#include <stdint.h>
#include <stddef.h>

// ---------------------------------------------------------------------------
// TWSABlock round 17 == round 15 (best measured: 728.2 us).
// hgemm: 128x128, BK=64, 3-stage cp.async ring, 256 thr, 2 CTA/SM.
// dwconv: half2 sliding window, 3 CTA/SM. attention: mma + ldmatrix.trans,
// 3 CTA/SM. prep+input-convert merged. fp32 residual stream end-to-end.
// ---------------------------------------------------------------------------

#define HW 4096
#define NB 16
#define CC 256
#define NTOK (NB * HW)
#define EPS 1e-5f

// ============================ small helpers ================================
__device__ __forceinline__ uint32_t smem_u32(const void* p) {
    uint32_t a;
    asm("{ .reg .u64 t; cvta.to.shared.u64 t, %1; cvt.u32.u64 %0, t; }"
        : "=r"(a) : "l"(p));
    return a;
}
__device__ __forceinline__ void ldsm4(uint32_t addr, uint32_t* r) {
    asm volatile("ldmatrix.sync.aligned.m8n8.x4.shared.b16 {%0,%1,%2,%3}, [%4];"
                 : "=r"(r[0]), "=r"(r[1]), "=r"(r[2]), "=r"(r[3]) : "r"(addr));
}
__device__ __forceinline__ void ldsm4t(uint32_t addr, uint32_t* r) {
    asm volatile("ldmatrix.sync.aligned.m8n8.x4.trans.shared.b16 {%0,%1,%2,%3}, [%4];"
                 : "=r"(r[0]), "=r"(r[1]), "=r"(r[2]), "=r"(r[3]) : "r"(addr));
}
__device__ __forceinline__ void mma16816(float* c, const uint32_t* a,
                                         uint32_t b0, uint32_t b1) {
    asm volatile(
        "mma.sync.aligned.m16n8k16.row.col.f32.f16.f16.f32 "
        "{%0,%1,%2,%3}, {%4,%5,%6,%7}, {%8,%9}, {%0,%1,%2,%3};"
        : "+f"(c[0]), "+f"(c[1]), "+f"(c[2]), "+f"(c[3])
        : "r"(a[0]), "r"(a[1]), "r"(a[2]), "r"(a[3]), "r"(b0), "r"(b1));
}
__device__ __forceinline__ uint32_t packh2(float a, float b) {
    __half2 t = __halves2half2(__float2half_rn(a), __float2half_rn(b));
    return *reinterpret_cast<uint32_t*>(&t);
}
#define CP_ASYNC16(dst, src) \
    asm volatile("cp.async.cg.shared.global [%0], [%1], 16;" :: "r"(dst), "l"(src))
#define CP_COMMIT() asm volatile("cp.async.commit_group;" ::: "memory")

// ============================== scratch ====================================
__device__ float g_x1[NTOK * CC];
__device__ float g_x2[NTOK * CC];
__device__ __half g_xh  [NTOK * CC];
__device__ __half g_t1h [NTOK * CC];
__device__ __half g_t2h [NTOK * CC];
__device__ __half g_x1nh[NTOK * CC];
__device__ __half g_qkvh[NTOK * 3 * CC];
__device__ __half g_obh [NTOK * CC];
__device__ __half g_x2nh[NTOK * CC];
__device__ __half g_hidh[NTOK * 4 * CC];
__device__ __half g_w1h[CC * CC];
__device__ __half g_w3h[CC * CC];
__device__ __half g_wph[CC * CC];
__device__ __half g_wqh[3 * CC * CC];
__device__ __half g_m1h[4 * CC * CC];
__device__ __half g_w2h[CC * 4 * CC];
__device__ float g_b1f[CC];
__device__ float g_dwf[CC * 9];
__device__ float g_dbf[CC];
__device__ float g_qkvbf[3 * CC];
__device__ float g_m1bf[4 * CC];

// ================== prep + input-convert (merged launch) ===================
__global__ void __launch_bounds__(256) prep_kernel(
    const float* __restrict__ conv1_w, const float* __restrict__ conv1_b,
    const float* __restrict__ bn1_g,  const float* __restrict__ bn1_b,
    const float* __restrict__ bn1_m,  const float* __restrict__ bn1_v,
    const float* __restrict__ dw_w,   const float* __restrict__ dw_b,
    const float* __restrict__ bn2_g,  const float* __restrict__ bn2_b,
    const float* __restrict__ bn2_m,  const float* __restrict__ bn2_v,
    const float* __restrict__ conv3_w,
    const float* __restrict__ proj_w,
    const float* __restrict__ mlp_w2,
    const float* __restrict__ qkv_w,  const float* __restrict__ qkv_b,
    const float* __restrict__ ln1_g,  const float* __restrict__ ln1_b,
    const float* __restrict__ mlp_w1, const float* __restrict__ mlp_b1,
    const float* __restrict__ ln2_g,  const float* __restrict__ ln2_b,
    const float* __restrict__ x, __half* __restrict__ xh)
{
    __shared__ float red[8];
    const int blk = blockIdx.x;
    const int tid = threadIdx.x;

    if (blk >= 1024) {
        __shared__ float sm[64 * 65];
        const int cid = blk - 1024;
        const int b  = cid >> 8;
        const int c0 = ((cid >> 6) & 3) * 64;
        const int p0 = (cid & 63) * 64;
        #pragma unroll
        for (int w = 0; w < 16; w++) {
            const int idx = tid + 256 * w;
            const int cl = idx >> 6, pl = idx & 63;
            sm[cl * 65 + pl] = x[((size_t)(b * 256 + c0 + cl)) * HW + p0 + pl];
        }
        __syncthreads();
        #pragma unroll
        for (int w = 0; w < 8; w++) {
            const int idx = tid + 256 * w;
            const int pl = idx >> 5, c2 = (idx & 31) * 2;
            const __half2 v = __halves2half2(
                __float2half_rn(sm[c2 * 65 + pl]),
                __float2half_rn(sm[(c2 + 1) * 65 + pl]));
            *reinterpret_cast<__half2*>(
                &xh[((size_t)(b * HW + p0 + pl)) * 256 + c0 + c2]) = v;
        }
        return;
    }

    const int r = blk;
    if (r < 256) {
        float inv1 = bn1_g[r] * rsqrtf(bn1_v[r] + EPS);
        g_w1h[r * 256 + tid] = __float2half_rn(conv1_w[r * 256 + tid] * inv1);
        g_w3h[r * 256 + tid] = __float2half_rn(conv3_w[r * 256 + tid]);
        g_wph[r * 256 + tid] = __float2half_rn(proj_w[r * 256 + tid]);
        #pragma unroll
        for (int k = 0; k < 4; k++)
            g_w2h[r * 1024 + tid + 256 * k] =
                __float2half_rn(mlp_w2[r * 1024 + tid + 256 * k]);
        if (tid == 0) g_b1f[r] = conv1_b[r] * inv1 + bn1_b[r] - bn1_m[r] * inv1;
        float inv2 = bn2_g[r] * rsqrtf(bn2_v[r] + EPS);
        if (tid < 9) g_dwf[r * 9 + tid] = dw_w[r * 9 + tid] * inv2;
        if (tid == 0) g_dbf[r] = dw_b[r] * inv2 + bn2_b[r] - bn2_m[r] * inv2;
    }
    if (r < 768) {
        float w = qkv_w[r * 256 + tid];
        g_wqh[r * 256 + tid] = __float2half_rn(w * ln1_g[tid]);
        float part = w * ln1_b[tid];
        #pragma unroll
        for (int o = 16; o; o >>= 1) part += __shfl_xor_sync(0xffffffffu, part, o);
        if ((tid & 31) == 0) red[tid >> 5] = part;
        __syncthreads();
        if (tid == 0) {
            float s = 0.f;
            #pragma unroll
            for (int w2 = 0; w2 < 8; w2++) s += red[w2];
            g_qkvbf[r] = qkv_b[r] + s;
        }
        __syncthreads();
    }
    if (r < 1024) {
        float w = mlp_w1[r * 256 + tid];
        g_m1h[r * 256 + tid] = __float2half_rn(w * ln2_g[tid]);
        float part = w * ln2_b[tid];
        #pragma unroll
        for (int o = 16; o; o >>= 1) part += __shfl_xor_sync(0xffffffffu, part, o);
        if ((tid & 31) == 0) red[tid >> 5] = part;
        __syncthreads();
        if (tid == 0) {
            float s = 0.f;
            #pragma unroll
            for (int w2 = 0; w2 < 8; w2++) s += red[w2];
            g_m1bf[r] = mlp_b1[r] + s;
        }
    }
}

// ========================= fp16 mma.sync GEMM ==============================
// Block 128x128, BK=64, 8 warps (4m x 2n), warp tile 32x64.
// 3-stage cp.async ring, ONE __syncthreads per iteration, prefetch depth 2.
constexpr int ROWB  = 144;
constexpr int PLANE = 128 * ROWB;          // 18432 B
constexpr int STAGE = 2 * PLANE;           // 36864 B (A, W)
constexpr int GEMM_SMEM = 3 * STAGE;       // 110592 B

// EP: 0 bias->fp16 ; 1 bias+res(tok fp32)->fp32 tok ; 2 gelu(bias)->fp16 ;
//     3 bias+res(NCHW fp32 via smem transpose)->fp32 tok ;
//     4 bias+res(tok fp32) -> NCHW fp32 out (smem transpose)
template<int K, int EP>
__global__ void __launch_bounds__(256, 2) hgemm(
    const __half* __restrict__ A, const __half* __restrict__ W,
    const float* __restrict__ bias, const float* __restrict__ res,
    float* __restrict__ outf, __half* __restrict__ outh, int N)
{
    extern __shared__ __align__(128) char smem[];
    const uint32_t sb = smem_u32(smem);
    const int n0  = blockIdx.x * 128;
    const int m0  = blockIdx.y * 128;
    const int tid = threadIdx.x;
    const int lane = tid & 31, wid = tid >> 5;
    const int wm = wid >> 1, wn = wid & 1;

    const char* srcA = (const char*)(A + (size_t)m0 * K);
    const char* srcW = (const char*)(W + (size_t)n0 * K);

    float c[2][8][4];
    #pragma unroll
    for (int i = 0; i < 2; i++)
        #pragma unroll
        for (int j = 0; j < 8; j++)
            #pragma unroll
            for (int r = 0; r < 4; r++) c[i][j][r] = 0.f;

    auto load_stage = [&](int s, int buf) {
        const uint32_t dst0 = sb + (uint32_t)buf * STAGE;
        const int c0b = s * 128;
        #pragma unroll
        for (int j = 0; j < 4; ++j) {
            const int e = tid + 256 * j;
            const int row = e >> 3, q = e & 7;
            CP_ASYNC16(dst0 + row * ROWB + q * 16,
                       srcA + (size_t)row * (K * 2) + c0b + q * 16);
            CP_ASYNC16(dst0 + PLANE + row * ROWB + q * 16,
                       srcW + (size_t)row * (K * 2) + c0b + q * 16);
        }
        CP_COMMIT();
    };

    const uint32_t aoff = (uint32_t)((lane & 15) * ROWB + (lane >> 4) * 16
                                     + wm * 32 * ROWB);
    const uint32_t boff = (uint32_t)(((lane & 7) + ((lane >> 4) << 3)) * ROWB
                                     + ((lane >> 3) & 1) * 16 + wn * 64 * ROWB);

    constexpr int NS = K / 64;
    load_stage(0, 0);
    load_stage(1, 1);
    int cbuf = 0;
    for (int s = 0; s < NS; ++s) {
        if (s + 1 < NS) {
            asm volatile("cp.async.wait_group 1;" ::: "memory");
        } else {
            asm volatile("cp.async.wait_group 0;" ::: "memory");
        }
        __syncthreads();

        int nbuf = cbuf + 2; if (nbuf >= 3) nbuf -= 3;
        if (s + 2 < NS) load_stage(s + 2, nbuf); else CP_COMMIT();

        const uint32_t base = sb + (uint32_t)cbuf * STAGE;
        #pragma unroll
        for (int k16 = 0; k16 < 4; ++k16) {
            const uint32_t kb = k16 * 32;
            uint32_t a[2][4], b[4][4];
            #pragma unroll
            for (int mt = 0; mt < 2; ++mt)
                ldsm4(base + aoff + mt * 16 * ROWB + kb, a[mt]);
            #pragma unroll
            for (int np = 0; np < 4; ++np)
                ldsm4(base + PLANE + boff + np * 16 * ROWB + kb, b[np]);
            #pragma unroll
            for (int mt = 0; mt < 2; ++mt)
                #pragma unroll
                for (int nt = 0; nt < 8; ++nt)
                    mma16816(c[mt][nt], a[mt],
                             b[nt >> 1][(nt & 1) * 2], b[nt >> 1][(nt & 1) * 2 + 1]);
        }
        cbuf = cbuf + 1; if (cbuf >= 3) cbuf -= 3;
    }
    __syncthreads();

    // ------------------------------ epilogue -------------------------------
    const int gr = lane >> 2, gc = (lane & 3) << 1;

    if (EP <= 2) {
        #pragma unroll
        for (int mt = 0; mt < 2; ++mt) {
            #pragma unroll
            for (int nt = 0; nt < 8; ++nt) {
                const int n = n0 + wn * 64 + nt * 8 + gc;
                const float2 b2 = *reinterpret_cast<const float2*>(&bias[n]);
                #pragma unroll
                for (int rh = 0; rh < 2; ++rh) {
                    const int m = m0 + wm * 32 + mt * 16 + gr + rh * 8;
                    float vx = c[mt][nt][rh * 2 + 0] + b2.x;
                    float vy = c[mt][nt][rh * 2 + 1] + b2.y;
                    const size_t off = (size_t)m * N + n;
                    if (EP == 1) {
                        const float2 r2 = *reinterpret_cast<const float2*>(&res[off]);
                        float2 o; o.x = vx + r2.x; o.y = vy + r2.y;
                        *reinterpret_cast<float2*>(&outf[off]) = o;
                    } else {
                        if (EP == 2) {
                            vx = vx * normcdff(vx);
                            vy = vy * normcdff(vy);
                        }
                        *reinterpret_cast<__half2*>(&outh[off]) =
                            __halves2half2(__float2half_rn(vx), __float2half_rn(vy));
                    }
                }
            }
        }
    } else if (EP == 3) {
        float* Rs = reinterpret_cast<float*>(smem);
        const int bb = m0 >> 12, p0 = m0 & 4095;
        #pragma unroll
        for (int nh = 0; nh < 2; ++nh) {
            __syncthreads();
            for (int e = tid; e < 2048; e += 256) {
                const int row = e >> 5, q = e & 31;
                *reinterpret_cast<float4*>(&Rs[row * 132 + q * 4]) =
                    *reinterpret_cast<const float4*>(
                        &res[((size_t)(bb * 256 + n0 + nh * 64 + row)) * HW + p0 + q * 4]);
            }
            __syncthreads();
            if (wn == nh) {
                #pragma unroll
                for (int mt = 0; mt < 2; ++mt) {
                    #pragma unroll
                    for (int nt = 0; nt < 8; ++nt) {
                        const int nl = nt * 8 + gc;
                        const int n = n0 + wn * 64 + nl;
                        const float2 b2 = *reinterpret_cast<const float2*>(&bias[n]);
                        #pragma unroll
                        for (int rh = 0; rh < 2; ++rh) {
                            const int ml = wm * 32 + mt * 16 + gr + rh * 8;
                            float2 o;
                            o.x = c[mt][nt][rh * 2 + 0] + b2.x + Rs[nl * 132 + ml];
                            o.y = c[mt][nt][rh * 2 + 1] + b2.y + Rs[(nl + 1) * 132 + ml];
                            *reinterpret_cast<float2*>(&outf[(size_t)(m0 + ml) * 256 + n]) = o;
                        }
                    }
                }
            }
        }
    } else {  // EP == 4
        float* Cs = reinterpret_cast<float*>(smem);
        const int bb = m0 >> 12, p0 = m0 & 4095;
        #pragma unroll
        for (int nh = 0; nh < 2; ++nh) {
            __syncthreads();
            if (wn == nh) {
                #pragma unroll
                for (int mt = 0; mt < 2; ++mt) {
                    #pragma unroll
                    for (int nt = 0; nt < 8; ++nt) {
                        const int nl = nt * 8 + gc;
                        const int n = n0 + wn * 64 + nl;
                        const float2 b2 = *reinterpret_cast<const float2*>(&bias[n]);
                        #pragma unroll
                        for (int rh = 0; rh < 2; ++rh) {
                            const int ml = wm * 32 + mt * 16 + gr + rh * 8;
                            const size_t roff = (size_t)(m0 + ml) * 256 + n;
                            const float2 r2 = *reinterpret_cast<const float2*>(&res[roff]);
                            Cs[nl * 132 + ml]       = c[mt][nt][rh * 2 + 0] + b2.x + r2.x;
                            Cs[(nl + 1) * 132 + ml] = c[mt][nt][rh * 2 + 1] + b2.y + r2.y;
                        }
                    }
                }
            }
            __syncthreads();
            for (int e = tid; e < 2048; e += 256) {
                const int row = e >> 5, q = e & 31;
                *reinterpret_cast<float4*>(
                    &outf[((size_t)(bb * 256 + n0 + nh * 64 + row)) * HW + p0 + q * 4]) =
                    *reinterpret_cast<const float4*>(&Cs[row * 132 + q * 4]);
            }
        }
    }
}

// ============== dw conv 3x3 (sliding window, half2 datapath) ===============
__global__ void __launch_bounds__(256, 3) dwconv_kernel(
    const __half* __restrict__ in, __half* __restrict__ oh)
{
    const int by = blockIdx.x;
    const int b = by >> 6, y = by & 63;
    const int tid = threadIdx.x;
    const int c4 = tid & 63;
    const int xq = tid >> 6;

    __half2 w2[9][2];
    #pragma unroll
    for (int k = 0; k < 9; k++)
        #pragma unroll
        for (int j = 0; j < 2; j++)
            w2[k][j] = __floats2half2_rn(g_dwf[(c4 * 4 + 2 * j) * 9 + k],
                                         g_dwf[(c4 * 4 + 2 * j + 1) * 9 + k]);
    const __half2 bs0 = __floats2half2_rn(g_dbf[c4 * 4],     g_dbf[c4 * 4 + 1]);
    const __half2 bs1 = __floats2half2_rn(g_dbf[c4 * 4 + 2], g_dbf[c4 * 4 + 3]);

    const __half* pM = in + ((size_t)(b * HW + y * 64)) * 256 + c4 * 4;
    const __half* pU = pM - 64 * 256;
    const __half* pD = pM + 64 * 256;
    const bool hasU = y > 0, hasD = y < 63;

    __half2 L[3][2], M[3][2], R[3][2];
    const __half2 z2 = __float2half2_rn(0.f);

    auto loadcol = [&](int xx, __half2 col[3][2]) {
        #pragma unroll
        for (int r = 0; r < 3; r++) {
            const bool ok = (r == 0) ? hasU : ((r == 2) ? hasD : true);
            if (ok) {
                const __half* p = (r == 0) ? pU : ((r == 1) ? pM : pD);
                const uint2 u = *reinterpret_cast<const uint2*>(p + xx * 256);
                col[r][0] = *reinterpret_cast<const __half2*>(&u.x);
                col[r][1] = *reinterpret_cast<const __half2*>(&u.y);
            } else {
                col[r][0] = z2;
                col[r][1] = z2;
            }
        }
    };

    const int x0 = xq * 16;
    if (x0 > 0) loadcol(x0 - 1, L);
    else {
        #pragma unroll
        for (int r = 0; r < 3; r++) { L[r][0] = z2; L[r][1] = z2; }
    }
    loadcol(x0, M);

    #pragma unroll
    for (int xi = 0; xi < 16; ++xi) {
        const int x = x0 + xi;
        if (x < 63) loadcol(x + 1, R);
        else {
            #pragma unroll
            for (int r = 0; r < 3; r++) { R[r][0] = z2; R[r][1] = z2; }
        }
        __half2 a0 = bs0, a1 = bs1;
        #pragma unroll
        for (int r = 0; r < 3; r++) {
            a0 = __hfma2(w2[r * 3 + 0][0], L[r][0], a0);
            a1 = __hfma2(w2[r * 3 + 0][1], L[r][1], a1);
            a0 = __hfma2(w2[r * 3 + 1][0], M[r][0], a0);
            a1 = __hfma2(w2[r * 3 + 1][1], M[r][1], a1);
            a0 = __hfma2(w2[r * 3 + 2][0], R[r][0], a0);
            a1 = __hfma2(w2[r * 3 + 2][1], R[r][1], a1);
        }
        uint2 uo;
        uo.x = *reinterpret_cast<uint32_t*>(&a0);
        uo.y = *reinterpret_cast<uint32_t*>(&a1);
        *reinterpret_cast<uint2*>(
            const_cast<__half*>(oh + ((size_t)(b * HW + y * 64 + x)) * 256 + c4 * 4)) = uo;
        #pragma unroll
        for (int r = 0; r < 3; r++) {
            L[r][0] = M[r][0]; L[r][1] = M[r][1];
            M[r][0] = R[r][0]; M[r][1] = R[r][1];
        }
    }
}

// ===================== LayerNorm + fp16 convert ============================
__global__ void __launch_bounds__(256) ln_split(
    const float* __restrict__ x, __half* __restrict__ oh)
{
    const int warp = threadIdx.x >> 5, lane = threadIdx.x & 31;
    const int tok = blockIdx.x * 8 + warp;
    const float* row = x + (size_t)tok * 256;
    const float4 v0 = *reinterpret_cast<const float4*>(&row[lane * 8]);
    const float4 v1 = *reinterpret_cast<const float4*>(&row[lane * 8 + 4]);
    float s = v0.x + v0.y + v0.z + v0.w + v1.x + v1.y + v1.z + v1.w;
    float s2 = v0.x * v0.x + v0.y * v0.y + v0.z * v0.z + v0.w * v0.w
             + v1.x * v1.x + v1.y * v1.y + v1.z * v1.z + v1.w * v1.w;
    #pragma unroll
    for (int o = 16; o; o >>= 1) {
        s  += __shfl_xor_sync(0xffffffffu, s,  o);
        s2 += __shfl_xor_sync(0xffffffffu, s2, o);
    }
    const float mu = s * (1.f / 256.f);
    const float rs = rsqrtf(s2 * (1.f / 256.f) - mu * mu + EPS);

    float v[8] = {v0.x, v0.y, v0.z, v0.w, v1.x, v1.y, v1.z, v1.w};
    uint4 uh;
    uh.x = packh2((v[0] - mu) * rs, (v[1] - mu) * rs);
    uh.y = packh2((v[2] - mu) * rs, (v[3] - mu) * rs);
    uh.z = packh2((v[4] - mu) * rs, (v[5] - mu) * rs);
    uh.w = packh2((v[6] - mu) * rs, (v[7] - mu) * rs);
    *reinterpret_cast<uint4*>(&oh[(size_t)tok * 256 + lane * 8]) = uh;
}

// ================== window attention on tensor cores =======================
constexpr int APAD  = 72;
constexpr int APADB = APAD * 2;
constexpr int HEAD_SMEM = 2 * 64 * APADB;
constexpr int ATTN_SMEM = 4 * HEAD_SMEM;     // 73728 B

__global__ void __launch_bounds__(128, 3) attn_mma(
    const __half* __restrict__ qkv, __half* __restrict__ oh)
{
    extern __shared__ __align__(128) char asmem[];
    const int win = blockIdx.x;
    const int b = win >> 6, wrem = win & 63;
    const int pbase = b * HW + (wrem >> 3) * 512 + (wrem & 7) * 8;
    const int tid = threadIdx.x;
    const int wid = tid >> 5, lane = tid & 31;
    const int gr = lane >> 2, gc = (lane & 3) << 1;

    const uint32_t qbase = smem_u32(asmem) + wid * HEAD_SMEM;
    const uint32_t kbase = qbase + 64 * APADB;
    __half* Qs = reinterpret_cast<__half*>(asmem) + wid * (HEAD_SMEM / 2);
    __half* Ks = Qs + 64 * APAD;

    const int qo = wid * 64, ko = 256 + wid * 64, vo = 512 + wid * 64;

    for (int e = lane; e < 512; e += 32) {
        const int t = e >> 3, q = e & 7;
        const int p = pbase + ((t >> 3) << 6) + (t & 7);
        *reinterpret_cast<uint4*>(&Qs[t * APAD + q * 8]) =
            *reinterpret_cast<const uint4*>(&qkv[(size_t)p * 768 + qo + q * 8]);
        *reinterpret_cast<uint4*>(&Ks[t * APAD + q * 8]) =
            *reinterpret_cast<const uint4*>(&qkv[(size_t)p * 768 + ko + q * 8]);
    }
    __syncwarp();

    const uint32_t aoff = (uint32_t)((lane & 15) * APADB + (lane >> 4) * 16);
    const uint32_t boff = (uint32_t)(((lane & 7) + ((lane >> 4) << 3)) * APADB
                                     + ((lane >> 3) & 1) * 16);

    float s[4][8][4];
    #pragma unroll
    for (int i = 0; i < 4; i++)
        #pragma unroll
        for (int j = 0; j < 8; j++)
            #pragma unroll
            for (int r = 0; r < 4; r++) s[i][j][r] = 0.f;

    #pragma unroll
    for (int k16 = 0; k16 < 4; ++k16) {
        const uint32_t kb = k16 * 32;
        uint32_t a[4][4], bf[4][4];
        #pragma unroll
        for (int mt = 0; mt < 4; ++mt)
            ldsm4(qbase + aoff + mt * 16 * APADB + kb, a[mt]);
        #pragma unroll
        for (int np = 0; np < 4; ++np)
            ldsm4(kbase + boff + np * 16 * APADB + kb, bf[np]);
        #pragma unroll
        for (int mt = 0; mt < 4; ++mt)
            #pragma unroll
            for (int nt = 0; nt < 8; ++nt)
                mma16816(s[mt][nt], a[mt],
                         bf[nt >> 1][(nt & 1) * 2], bf[nt >> 1][(nt & 1) * 2 + 1]);
    }

    const float sc = 0.125f;
    #pragma unroll
    for (int mt = 0; mt < 4; ++mt) {
        #pragma unroll
        for (int rh = 0; rh < 2; ++rh) {
            float mx = -1e30f;
            #pragma unroll
            for (int nt = 0; nt < 8; ++nt) {
                s[mt][nt][rh * 2]     *= sc;
                s[mt][nt][rh * 2 + 1] *= sc;
                mx = fmaxf(mx, fmaxf(s[mt][nt][rh * 2], s[mt][nt][rh * 2 + 1]));
            }
            mx = fmaxf(mx, __shfl_xor_sync(0xffffffffu, mx, 1));
            mx = fmaxf(mx, __shfl_xor_sync(0xffffffffu, mx, 2));
            float sum = 0.f;
            #pragma unroll
            for (int nt = 0; nt < 8; ++nt) {
                s[mt][nt][rh * 2]     = __expf(s[mt][nt][rh * 2] - mx);
                s[mt][nt][rh * 2 + 1] = __expf(s[mt][nt][rh * 2 + 1] - mx);
                sum += s[mt][nt][rh * 2] + s[mt][nt][rh * 2 + 1];
            }
            sum += __shfl_xor_sync(0xffffffffu, sum, 1);
            sum += __shfl_xor_sync(0xffffffffu, sum, 2);
            const float inv = 1.f / sum;
            #pragma unroll
            for (int nt = 0; nt < 8; ++nt) {
                s[mt][nt][rh * 2]     *= inv;
                s[mt][nt][rh * 2 + 1] *= inv;
            }
        }
    }

    uint32_t ap[4][4][4];
    #pragma unroll
    for (int mt = 0; mt < 4; ++mt)
        #pragma unroll
        for (int kt = 0; kt < 4; ++kt) {
            ap[mt][kt][0] = packh2(s[mt][2 * kt][0],     s[mt][2 * kt][1]);
            ap[mt][kt][1] = packh2(s[mt][2 * kt][2],     s[mt][2 * kt][3]);
            ap[mt][kt][2] = packh2(s[mt][2 * kt + 1][0], s[mt][2 * kt + 1][1]);
            ap[mt][kt][3] = packh2(s[mt][2 * kt + 1][2], s[mt][2 * kt + 1][3]);
        }

    // reuse s as O accumulator
    #pragma unroll
    for (int i = 0; i < 4; i++)
        #pragma unroll
        for (int j = 0; j < 8; j++)
            #pragma unroll
            for (int r = 0; r < 4; r++) s[i][j][r] = 0.f;

    __syncwarp();
    for (int e = lane; e < 512; e += 32) {
        const int t = e >> 3, q = e & 7;
        const int p = pbase + ((t >> 3) << 6) + (t & 7);
        *reinterpret_cast<uint4*>(&Ks[t * APAD + q * 8]) =
            *reinterpret_cast<const uint4*>(&qkv[(size_t)p * 768 + vo + q * 8]);
    }
    __syncwarp();

    const uint32_t vtoff = (uint32_t)((lane & 15) * APADB + (lane >> 4) * 16);

    #pragma unroll
    for (int kt = 0; kt < 4; ++kt) {
        uint32_t bf[4][4];
        #pragma unroll
        for (int np = 0; np < 4; ++np)
            ldsm4t(kbase + vtoff + kt * 16 * APADB + np * 32, bf[np]);
        #pragma unroll
        for (int mt = 0; mt < 4; ++mt)
            #pragma unroll
            for (int nt = 0; nt < 8; ++nt)
                mma16816(s[mt][nt], ap[mt][kt],
                         bf[nt >> 1][(nt & 1) * 2], bf[nt >> 1][(nt & 1) * 2 + 1]);
    }

    #pragma unroll
    for (int mt = 0; mt < 4; ++mt)
        #pragma unroll
        for (int rh = 0; rh < 2; ++rh) {
            const int t = mt * 16 + gr + rh * 8;
            const int p = pbase + ((t >> 3) << 6) + (t & 7);
            #pragma unroll
            for (int nt = 0; nt < 8; ++nt) {
                const int d = nt * 8 + gc;
                *reinterpret_cast<__half2*>(&oh[(size_t)p * 256 + qo + d]) =
                    __halves2half2(__float2half_rn(s[mt][nt][rh * 2]),
                                   __float2half_rn(s[mt][nt][rh * 2 + 1]));
            }
        }
}

// =============================== launcher ==================================
extern "C" void kernel_launch(void* const* d_in, const int* in_sizes, int n_in,
                              void* d_out, int out_size)
{
    (void)in_sizes; (void)n_in; (void)out_size;
    const float* x       = (const float*)d_in[0];
    const float* conv1_w = (const float*)d_in[1];
    const float* conv1_b = (const float*)d_in[2];
    const float* bn1_g   = (const float*)d_in[3];
    const float* bn1_b   = (const float*)d_in[4];
    const float* bn1_m   = (const float*)d_in[5];
    const float* bn1_v   = (const float*)d_in[6];
    const float* dw_w    = (const float*)d_in[7];
    const float* dw_b    = (const float*)d_in[8];
    const float* bn2_g   = (const float*)d_in[9];
    const float* bn2_b   = (const float*)d_in[10];
    const float* bn2_m   = (const float*)d_in[11];
    const float* bn2_v   = (const float*)d_in[12];
    const float* conv3_w = (const float*)d_in[13];
    const float* conv3_b = (const float*)d_in[14];
    const float* ln1_g   = (const float*)d_in[15];
    const float* ln1_b   = (const float*)d_in[16];
    const float* qkv_w   = (const float*)d_in[17];
    const float* qkv_b   = (const float*)d_in[18];
    const float* proj_w  = (const float*)d_in[19];
    const float* proj_b  = (const float*)d_in[20];
    const float* ln2_g   = (const float*)d_in[21];
    const float* ln2_b   = (const float*)d_in[22];
    const float* mlp_w1  = (const float*)d_in[23];
    const float* mlp_b1  = (const float*)d_in[24];
    const float* mlp_w2  = (const float*)d_in[25];
    const float* mlp_b2  = (const float*)d_in[26];
    float* out = (float*)d_out;

    float *x1, *x2, *b1f, *qkvbf, *m1bf;
    __half *xh, *t1h, *t2h, *x1nh, *qkvh, *obh, *x2nh, *hidh;
    __half *w1h, *w3h, *wph, *wqh, *m1h, *w2h;
    cudaGetSymbolAddress((void**)&x1,   g_x1);
    cudaGetSymbolAddress((void**)&x2,   g_x2);
    cudaGetSymbolAddress((void**)&xh,   g_xh);
    cudaGetSymbolAddress((void**)&t1h,  g_t1h);
    cudaGetSymbolAddress((void**)&t2h,  g_t2h);
    cudaGetSymbolAddress((void**)&x1nh, g_x1nh);
    cudaGetSymbolAddress((void**)&qkvh, g_qkvh);
    cudaGetSymbolAddress((void**)&obh,  g_obh);
    cudaGetSymbolAddress((void**)&x2nh, g_x2nh);
    cudaGetSymbolAddress((void**)&hidh, g_hidh);
    cudaGetSymbolAddress((void**)&w1h,  g_w1h);
    cudaGetSymbolAddress((void**)&w3h,  g_w3h);
    cudaGetSymbolAddress((void**)&wph,  g_wph);
    cudaGetSymbolAddress((void**)&wqh,  g_wqh);
    cudaGetSymbolAddress((void**)&m1h,  g_m1h);
    cudaGetSymbolAddress((void**)&w2h,  g_w2h);
    cudaGetSymbolAddress((void**)&b1f,   g_b1f);
    cudaGetSymbolAddress((void**)&qkvbf, g_qkvbf);
    cudaGetSymbolAddress((void**)&m1bf,  g_m1bf);

    cudaFuncSetAttribute(hgemm<256, 0>,
        cudaFuncAttributeMaxDynamicSharedMemorySize, GEMM_SMEM);
    cudaFuncSetAttribute(hgemm<256, 1>,
        cudaFuncAttributeMaxDynamicSharedMemorySize, GEMM_SMEM);
    cudaFuncSetAttribute(hgemm<256, 2>,
        cudaFuncAttributeMaxDynamicSharedMemorySize, GEMM_SMEM);
    cudaFuncSetAttribute(hgemm<256, 3>,
        cudaFuncAttributeMaxDynamicSharedMemorySize, GEMM_SMEM);
    cudaFuncSetAttribute(hgemm<1024, 4>,
        cudaFuncAttributeMaxDynamicSharedMemorySize, GEMM_SMEM);
    cudaFuncSetAttribute(attn_mma,
        cudaFuncAttributeMaxDynamicSharedMemorySize, ATTN_SMEM);

    // 0) prep (weights) + input convert, single launch
    prep_kernel<<<5120, 256>>>(conv1_w, conv1_b, bn1_g, bn1_b, bn1_m, bn1_v,
                               dw_w, dw_b, bn2_g, bn2_b, bn2_m, bn2_v,
                               conv3_w, proj_w, mlp_w2,
                               qkv_w, qkv_b, ln1_g, ln1_b,
                               mlp_w1, mlp_b1, ln2_g, ln2_b,
                               x, xh);

    // 1) conv1 + BN1 -> t1 fp16
    hgemm<256, 0><<<dim3(2, 512), 256, GEMM_SMEM>>>(
        xh, w1h, b1f, nullptr, nullptr, t1h, 256);
    // 2) dw3x3 + BN2 -> t2 fp16 (half2 datapath, 3 CTA/SM)
    dwconv_kernel<<<1024, 256>>>(t1h, t2h);
    // 3) conv3 + residual(x NCHW) -> x1 fp32 token-major
    hgemm<256, 3><<<dim3(2, 512), 256, GEMM_SMEM>>>(
        t2h, w3h, conv3_b, x, x1, nullptr, 256);
    // 4) LN1 -> x1n fp16
    ln_split<<<8192, 256>>>(x1, x1nh);
    // 5) QKV -> qkv fp16 [tok][768]
    hgemm<256, 0><<<dim3(6, 512), 256, GEMM_SMEM>>>(
        x1nh, wqh, qkvbf, nullptr, nullptr, qkvh, 768);
    // 6) window attention (tensor cores) -> ob fp16
    attn_mma<<<1024, 128, ATTN_SMEM>>>(qkvh, obh);
    // 7) proj + residual(x1) -> x2 fp32
    hgemm<256, 1><<<dim3(2, 512), 256, GEMM_SMEM>>>(
        obh, wph, proj_b, x1, x2, nullptr, 256);
    // 8) LN2 -> x2n fp16
    ln_split<<<8192, 256>>>(x2, x2nh);
    // 9) MLP1 + GELU -> hid fp16 [tok][1024]
    hgemm<256, 2><<<dim3(8, 512), 256, GEMM_SMEM>>>(
        x2nh, m1h, m1bf, nullptr, nullptr, hidh, 1024);
    // 10) MLP2 + residual(x2) -> out NCHW fp32
    hgemm<1024, 4><<<dim3(2, 512), 256, GEMM_SMEM>>>(
        hidh, w2h, mlp_b2, x2, out, nullptr, 256);
}